// round 3
// baseline (speedup 1.0000x reference)
#include <cuda_runtime.h>
#include <cuda_bf16.h>

// WCSS: loss = mean_k [ (S2_k - ||S1_k||^2 / n_k) / (n_k * D) ]
//   S1_k[d] = sum_{i: y_i=k} X[i,d]   (per-class column sums, D = C*T)
//   S2_k    = sum_{i: y_i=k} ||x_i||^2
//
// y_true is read as int32: JAX silently downcasts jnp.int64 -> int32 when
// x64 is disabled (default), so the dumped buffer is int32. Reading it as
// int64 caused R1's OOB fault and R2's 9% error (garbage tiny classes).
//
// Pass 1 (accum): stream X once (201 MB), privatize per-class {sum, sumsq}
// per column in shared memory (class id is warp-uniform per row -> no
// races, no bank conflicts), flush with spread float atomics (S1) and one
// double atomic per (block, class) (S2).
// Pass 2 (finalize): 1 block -> label histogram, ||S1_k||^2, closed form.
// K is derived as (max label + 1); num_classes input is never dereferenced.

#define CHUNK 256          // columns per block == threads per block
#define KMAX  16           // max classes supported (problem uses 10)
#define DMAX  8192         // max D supported (problem uses 6144)

__device__ float  g_sums[KMAX * DMAX];   // per-class column sums
__device__ double g_S2[KMAX];            // per-class sum of squares

// ---------------------------------------------------------------------------
__global__ void wcss_zero(int D)
{
    int n = KMAX * D;
    for (int i = blockIdx.x * blockDim.x + threadIdx.x; i < n;
         i += gridDim.x * blockDim.x)
        g_sums[i] = 0.0f;
    if (blockIdx.x == 0 && threadIdx.x < KMAX)
        g_S2[threadIdx.x] = 0.0;
}

// ---------------------------------------------------------------------------
__global__ __launch_bounds__(CHUNK)
void wcss_accum(const float* __restrict__ X,
                const int* __restrict__ y,
                int N, int D, int rowsPerBlk)
{
    // acc[k][c] = {sum, sumsq} for class k, column c (within this block's
    // column chunk). float2 -> one LDS.64/STS.64 pair per element.
    __shared__ float2 acc[KMAX][CHUNK];

    const int tid = threadIdx.x;
    const int d   = blockIdx.x * CHUNK + tid;
    const int r0  = blockIdx.y * rowsPerBlk;
    const int r1  = min(N, r0 + rowsPerBlk);
    const bool valid = (d < D);

    #pragma unroll
    for (int k = 0; k < KMAX; k++)
        acc[k][tid] = make_float2(0.0f, 0.0f);
    __syncthreads();

    if (valid) {
        const float* xp = X + (size_t)r0 * D + d;
        for (int i = r0; i < r1; i++) {
            int   c = __ldg(&y[i]) & (KMAX - 1);  // warp-uniform; clamp
            float x = __ldg(xp);
            float2 a = acc[c][tid];
            a.x += x;
            a.y += x * x;
            acc[c][tid] = a;
            xp += D;
        }
    }
    __syncthreads();

    // Flush per-class column sums (spread-address float atomics).
    // All KMAX slots: unused classes hold zeros, harmless.
    if (valid) {
        #pragma unroll
        for (int k = 0; k < KMAX; k++)
            atomicAdd(&g_sums[k * D + d], acc[k][tid].x);
    }
    __syncthreads();

    // Block-reduce sumsq per class over the 256 columns, then one double
    // atomic per (block, class).
    for (int s = CHUNK / 2; s > 0; s >>= 1) {
        if (tid < s) {
            #pragma unroll
            for (int k = 0; k < KMAX; k++)
                acc[k][tid].y += acc[k][tid + s].y;
        }
        __syncthreads();
    }
    if (tid < KMAX)
        atomicAdd(&g_S2[tid], (double)acc[tid][0].y);
}

// ---------------------------------------------------------------------------
__global__ void wcss_finalize(const int* __restrict__ y,
                              int N, int D, float* __restrict__ out)
{
    const int tid = threadIdx.x;

    __shared__ int    cnt[KMAX];
    __shared__ int    kmax_sh;
    __shared__ float  red[256];
    __shared__ double total_sh;
    __shared__ int    nclass_sh;

    if (tid < KMAX) cnt[tid] = 0;
    if (tid == 0) { total_sh = 0.0; kmax_sh = 0; nclass_sh = 0; }
    __syncthreads();

    int lmax = 0;
    for (int i = tid; i < N; i += blockDim.x) {
        int c = y[i] & (KMAX - 1);
        atomicAdd(&cnt[c], 1);
        lmax = max(lmax, c);
    }
    atomicMax(&kmax_sh, lmax);
    __syncthreads();

    const int K = kmax_sh + 1;   // num_classes = max label + 1

    for (int k = 0; k < K; k++) {
        float m2 = 0.0f;
        const float* sk = &g_sums[k * D];
        for (int dd = tid; dd < D; dd += blockDim.x) {
            float v = sk[dd];
            m2 += v * v;
        }
        red[tid] = m2;
        __syncthreads();
        for (int s = 128; s > 0; s >>= 1) {
            if (tid < s) red[tid] += red[tid + s];
            __syncthreads();
        }
        if (tid == 0 && cnt[k] > 0) {
            double n  = (double)cnt[k];
            double lk = (g_S2[k] - (double)red[0] / n) / (n * (double)D);
            total_sh += lk;
            nclass_sh += 1;
        }
        __syncthreads();
    }

    if (tid == 0)
        out[0] = (float)(total_sh / (double)max(nclass_sh, 1));
}

// ---------------------------------------------------------------------------
extern "C" void kernel_launch(void* const* d_in, const int* in_sizes, int n_in,
                              void* d_out, int out_size)
{
    const float* X   = (const float*)d_in[0];
    const int*   y   = (const int*)d_in[1];   // int32 (JAX x64 disabled)
    float*       out = (float*)d_out;

    const int total = in_sizes[0];          // N * C * T
    const int N     = in_sizes[1];          // 8192
    const int D     = total / N;            // 6144

    // Zero scratch
    {
        int n = KMAX * D;
        int blocks = (n + 255) / 256;
        wcss_zero<<<blocks, 256>>>(D);
    }

    // Main streaming pass: grid = (column chunks) x (row chunks)
    {
        int chunks      = (D + CHUNK - 1) / CHUNK;   // 24
        int rowsPerBlk  = 512;
        int rowBlks     = (N + rowsPerBlk - 1) / rowsPerBlk;  // 16
        dim3 grid(chunks, rowBlks);
        wcss_accum<<<grid, CHUNK>>>(X, y, N, D, rowsPerBlk);
    }

    // Finalize
    wcss_finalize<<<1, 256>>>(y, N, D, out);
}

// round 4
// speedup vs baseline: 1.1036x; 1.1036x over previous
#include <cuda_runtime.h>
#include <cuda_bf16.h>

// WCSS: loss = mean_k [ (S2_k - ||S1_k||^2 / n_k) / (n_k * D) ]
//   S1_k[d] = sum_{i: y_i=k} X[i,d],  S2_k = sum_{i: y_i=k} ||x_i||^2
//
// R3 was latency-bound (MLP=1: smem RMW chain serialized the LDGs -> 1.3TB/s).
// R4: sort rows by class (one tiny block), then each main block owns ONE
// class segment -> accumulators in registers, 8-way batched LDGs, no smem
// in the hot loop. Pure streaming pass at the DRAM roofline.

#define CHUNK 256          // columns per block == threads per block
#define ROWS  256          // rows per segment
#define KMAX  16           // max classes (problem uses 10)
#define DMAX  8192         // max D (problem uses 6144)
#define NMAX  16384        // max N (problem uses 8192)
#define SEGS  32           // segments per class: SEGS*ROWS >= NMAX/2 (safe)

__device__ float  g_sums[KMAX * DMAX];   // per-class column sums
__device__ double g_S2[KMAX];            // per-class sum of squares
__device__ int    g_order[NMAX];         // row ids grouped by class
__device__ int    g_cnt[KMAX];
__device__ int    g_start[KMAX];

// ---------------------------------------------------------------------------
__global__ void wcss_zero(int D)
{
    int n = KMAX * D;
    for (int i = blockIdx.x * blockDim.x + threadIdx.x; i < n;
         i += gridDim.x * blockDim.x)
        g_sums[i] = 0.0f;
    if (blockIdx.x == 0 && threadIdx.x < KMAX)
        g_S2[threadIdx.x] = 0.0;
}

// ---------------------------------------------------------------------------
// One block: histogram -> prefix -> scatter row ids grouped by class.
__global__ void wcss_scatter(const int* __restrict__ y, int N)
{
    __shared__ int cnt[KMAX], off[KMAX];
    const int tid = threadIdx.x;

    if (tid < KMAX) cnt[tid] = 0;
    __syncthreads();

    for (int i = tid; i < N; i += blockDim.x)
        atomicAdd(&cnt[y[i] & (KMAX - 1)], 1);
    __syncthreads();

    if (tid == 0) {
        int acc = 0;
        for (int k = 0; k < KMAX; k++) {
            off[k] = acc; g_start[k] = acc; g_cnt[k] = cnt[k];
            acc += cnt[k];
        }
    }
    __syncthreads();

    for (int i = tid; i < N; i += blockDim.x) {
        int c = y[i] & (KMAX - 1);
        int pos = atomicAdd(&off[c], 1);
        if (pos < NMAX) g_order[pos] = i;
    }
}

// ---------------------------------------------------------------------------
// grid = (colChunks, KMAX, SEGS). Block (x, c, s): class c, rows
// [s*ROWS, s*ROWS+len) of its sorted segment, columns [x*CHUNK, ...).
// Register accumulators; one atomic flush per block.
__global__ __launch_bounds__(CHUNK)
void wcss_main(const float* __restrict__ X, int D)
{
    const int c    = blockIdx.y;
    const int cn   = g_cnt[c];
    const int base = blockIdx.z * ROWS;
    if (base >= cn) return;
    const int len  = min(ROWS, cn - base);

    const int tid = threadIdx.x;
    const int d   = blockIdx.x * CHUNK + tid;

    __shared__ int rows_sh[ROWS];
    if (tid < len) rows_sh[tid] = g_order[g_start[c] + base + tid];
    __syncthreads();

    float s0 = 0.f, s1 = 0.f, q0 = 0.f, q1 = 0.f;

    if (d < D) {
        int i = 0;
        for (; i + 8 <= len; i += 8) {
            float x[8];
            #pragma unroll
            for (int u = 0; u < 8; u++)
                x[u] = __ldg(&X[(size_t)rows_sh[i + u] * D + d]);
            #pragma unroll
            for (int u = 0; u < 8; u += 2) {
                s0 += x[u];     q0 = fmaf(x[u],     x[u],     q0);
                s1 += x[u + 1]; q1 = fmaf(x[u + 1], x[u + 1], q1);
            }
        }
        for (; i < len; i++) {
            float xv = __ldg(&X[(size_t)rows_sh[i] * D + d]);
            s0 += xv; q0 = fmaf(xv, xv, q0);
        }
        atomicAdd(&g_sums[c * D + d], s0 + s1);
    }

    // Block-reduce sumsq, one double atomic per block.
    float q = q0 + q1;
    #pragma unroll
    for (int o = 16; o > 0; o >>= 1)
        q += __shfl_down_sync(0xffffffffu, q, o);

    __shared__ float qs[CHUNK / 32];
    if ((tid & 31) == 0) qs[tid >> 5] = q;
    __syncthreads();
    if (tid < CHUNK / 32) {
        float v = qs[tid];
        #pragma unroll
        for (int o = CHUNK / 64; o > 0; o >>= 1)
            v += __shfl_down_sync(0xffu, v, o);
        if (tid == 0)
            atomicAdd(&g_S2[c], (double)v);
    }
}

// ---------------------------------------------------------------------------
__global__ void wcss_finalize(int D, float* __restrict__ out)
{
    const int tid = threadIdx.x;

    __shared__ float  red[256];
    __shared__ double total_sh;
    __shared__ int    nclass_sh;

    if (tid == 0) { total_sh = 0.0; nclass_sh = 0; }
    __syncthreads();

    for (int k = 0; k < KMAX; k++) {
        if (g_cnt[k] == 0) continue;
        float m2 = 0.0f;
        const float* sk = &g_sums[k * D];
        for (int dd = tid; dd < D; dd += blockDim.x) {
            float v = sk[dd];
            m2 = fmaf(v, v, m2);
        }
        red[tid] = m2;
        __syncthreads();
        for (int s = 128; s > 0; s >>= 1) {
            if (tid < s) red[tid] += red[tid + s];
            __syncthreads();
        }
        if (tid == 0) {
            double n  = (double)g_cnt[k];
            double lk = (g_S2[k] - (double)red[0] / n) / (n * (double)D);
            total_sh += lk;
            nclass_sh += 1;
        }
        __syncthreads();
    }

    if (tid == 0)
        out[0] = (float)(total_sh / (double)max(nclass_sh, 1));
}

// ---------------------------------------------------------------------------
extern "C" void kernel_launch(void* const* d_in, const int* in_sizes, int n_in,
                              void* d_out, int out_size)
{
    const float* X   = (const float*)d_in[0];
    const int*   y   = (const int*)d_in[1];   // int32 (JAX x64 disabled)
    float*       out = (float*)d_out;

    const int total = in_sizes[0];          // N * C * T
    const int N     = in_sizes[1];          // 8192
    const int D     = total / N;            // 6144

    // Zero scratch
    {
        int n = KMAX * D;
        wcss_zero<<<(n + 255) / 256, 256>>>(D);
    }

    // Group rows by class
    wcss_scatter<<<1, 256>>>(y, N);

    // Main streaming pass: register accumulators, one class per block
    {
        int chunks = (D + CHUNK - 1) / CHUNK;   // 24
        dim3 grid(chunks, KMAX, SEGS);
        wcss_main<<<grid, CHUNK>>>(X, D);
    }

    // Finalize
    wcss_finalize<<<1, 256>>>(D, out);
}

// round 5
// speedup vs baseline: 1.7153x; 1.5542x over previous
#include <cuda_runtime.h>
#include <cuda_bf16.h>

// WCSS: loss = mean_k [ (S2_k - ||S1_k||^2 / n_k) / (n_k * D) ]
//
// R4 post-mortem: single-block finalize over g_sums was 126us (latency-serial
// on 1 SM). R5: one block per (column-chunk, class) loops over the WHOLE
// class segment, so S1_k[d] completes in a register; the block squares and
// reduces in place -> 2 double atomics. No g_sums, no zero pass, no finalize
// scan. 240 resident blocks, 16-deep LDG batches to saturate DRAM.

#define CHUNK 256          // columns per block == threads per block
#define KMAX  16           // max classes (problem uses 10)
#define NMAX  16384        // max N (problem uses 8192)
#define BATCH 16           // independent LDGs per thread (MLP)

__device__ double g_S2[KMAX];     // per-class sum of squares
__device__ double g_M2[KMAX];     // per-class ||S1_k||^2
__device__ int    g_order[NMAX];  // row ids grouped by class
__device__ int    g_cnt[KMAX];
__device__ int    g_start[KMAX];

// ---------------------------------------------------------------------------
// One block: histogram -> prefix -> scatter row ids grouped by class.
// Also (re)zeroes the per-class accumulators (graph-replay safe).
__global__ void wcss_scatter(const int* __restrict__ y, int N)
{
    __shared__ int cnt[KMAX], off[KMAX];
    const int tid = threadIdx.x;

    if (tid < KMAX) { cnt[tid] = 0; g_S2[tid] = 0.0; g_M2[tid] = 0.0; }
    __syncthreads();

    for (int i = tid; i < N; i += blockDim.x)
        atomicAdd(&cnt[y[i] & (KMAX - 1)], 1);
    __syncthreads();

    if (tid == 0) {
        int acc = 0;
        for (int k = 0; k < KMAX; k++) {
            off[k] = acc; g_start[k] = acc; g_cnt[k] = cnt[k];
            acc += cnt[k];
        }
    }
    __syncthreads();

    for (int i = tid; i < N; i += blockDim.x) {
        int c = y[i] & (KMAX - 1);
        int pos = atomicAdd(&off[c], 1);
        if (pos < NMAX) g_order[pos] = i;
    }
}

// ---------------------------------------------------------------------------
// grid = (colChunks, KMAX). Block (x, c): class c, columns [x*CHUNK, ...),
// loops over ALL rows of class c. Register-complete column sums.
__global__ __launch_bounds__(CHUNK)
void wcss_main(const float* __restrict__ X, int D)
{
    const int c  = blockIdx.y;
    const int cn = g_cnt[c];
    if (cn == 0) return;
    const int st = g_start[c];

    const int tid = threadIdx.x;
    const int d   = blockIdx.x * CHUNK + tid;
    const bool valid = (d < D);

    __shared__ int rows_sh[CHUNK];

    float s0 = 0.f, s1 = 0.f, q0 = 0.f, q1 = 0.f;

    for (int base = 0; base < cn; base += CHUNK) {
        const int tl = min(CHUNK, cn - base);
        __syncthreads();                       // protect rows_sh reuse
        if (tid < tl) rows_sh[tid] = g_order[st + base + tid];
        __syncthreads();

        if (valid) {
            int i = 0;
            for (; i + BATCH <= tl; i += BATCH) {
                float x[BATCH];
                #pragma unroll
                for (int u = 0; u < BATCH; u++)
                    x[u] = __ldg(&X[(size_t)rows_sh[i + u] * D + d]);
                #pragma unroll
                for (int u = 0; u < BATCH; u += 2) {
                    s0 += x[u];     q0 = fmaf(x[u],     x[u],     q0);
                    s1 += x[u + 1]; q1 = fmaf(x[u + 1], x[u + 1], q1);
                }
            }
            for (; i < tl; i++) {
                float xv = __ldg(&X[(size_t)rows_sh[i] * D + d]);
                s0 += xv; q0 = fmaf(xv, xv, q0);
            }
        }
    }

    // Per-thread: full column sum s -> m2 contribution s^2; sumsq q.
    float s  = s0 + s1;
    float m2 = valid ? s * s : 0.f;
    float q  = q0 + q1;

    // Warp reduce both.
    #pragma unroll
    for (int o = 16; o > 0; o >>= 1) {
        m2 += __shfl_down_sync(0xffffffffu, m2, o);
        q  += __shfl_down_sync(0xffffffffu, q,  o);
    }

    __shared__ float ms[CHUNK / 32], qs[CHUNK / 32];
    if ((tid & 31) == 0) { ms[tid >> 5] = m2; qs[tid >> 5] = q; }
    __syncthreads();
    if (tid < 32) {
        float mv = (tid < CHUNK / 32) ? ms[tid] : 0.f;
        float qv = (tid < CHUNK / 32) ? qs[tid] : 0.f;
        #pragma unroll
        for (int o = CHUNK / 64; o > 0; o >>= 1) {
            mv += __shfl_down_sync(0xffffffffu, mv, o);
            qv += __shfl_down_sync(0xffffffffu, qv, o);
        }
        if (tid == 0) {
            atomicAdd(&g_M2[c], (double)mv);
            atomicAdd(&g_S2[c], (double)qv);
        }
    }
}

// ---------------------------------------------------------------------------
// Tiny scalar finalize: 1 warp.
__global__ void wcss_final(int D, float* __restrict__ out)
{
    if (threadIdx.x == 0) {
        double total = 0.0;
        int    nc    = 0;
        for (int k = 0; k < KMAX; k++) {
            int c = g_cnt[k];
            if (c == 0) continue;
            double n = (double)c;
            total += (g_S2[k] - g_M2[k] / n) / (n * (double)D);
            nc++;
        }
        out[0] = (float)(total / (double)(nc > 0 ? nc : 1));
    }
}

// ---------------------------------------------------------------------------
extern "C" void kernel_launch(void* const* d_in, const int* in_sizes, int n_in,
                              void* d_out, int out_size)
{
    const float* X   = (const float*)d_in[0];
    const int*   y   = (const int*)d_in[1];   // int32 (JAX x64 disabled)
    float*       out = (float*)d_out;

    const int total = in_sizes[0];          // N * C * T
    const int N     = in_sizes[1];          // 8192
    const int D     = total / N;            // 6144

    // Group rows by class + zero accumulators
    wcss_scatter<<<1, 1024>>>(y, N);

    // Main streaming pass: one block per (column chunk, class)
    {
        int chunks = (D + CHUNK - 1) / CHUNK;   // 24
        dim3 grid(chunks, KMAX);
        wcss_main<<<grid, CHUNK>>>(X, D);
    }

    // Scalar finalize
    wcss_final<<<1, 32>>>(D, out);
}